// round 16
// baseline (speedup 1.0000x reference)
#include <cuda_runtime.h>
#include <cuda_fp16.h>
#include <math.h>
#include <float.h>

#define NN 100000
#define EE 400000
#define GG 4096
#define EMB 128
#define LN2F 0.6931471805599453f

// ---------------- scratch ----------------
__device__ float  g_ha  [NN * EMB];
__device__ float  g_hb  [NN * EMB];
__device__ float  g_PQ  [NN * 2 * EMB];     // [P | Q], pitch 256
__device__ __half g_hbh [NN * EMB];         // fp16 hi plane of h_b
__device__ __half g_hbl [NN * EMB];         // fp16 lo plane of h_b
__device__ __half g_Xh  [NN * 2 * EMB];     // fp16 hi plane of X=[U|T]
__device__ __half g_Xl  [NN * 2 * EMB];     // fp16 lo plane of X
__device__ __half g_combh[2 * EMB * EMB];   // W' = [W1-W2|W2]^T : [256][128]
__device__ __half g_combl[2 * EMB * EMB];
__device__ __half g_wcath[2 * EMB * EMB];   // Wcat^T : [128][256]
__device__ __half g_wcatl[2 * EMB * EMB];
__device__ int    g_deg [NN];
__device__ int    g_off [NN + 1];
__device__ int    g_fill[NN];
__device__ int    g_bsumA[128];
__device__ int    g_boff [128];
__device__ int    g_csr_src[EE];
__device__ int    g_csr_eid[EE];
__device__ int    g_gstart[GG + 1];

__device__ __forceinline__ float sp(float x) {
    return fmaxf(x, 0.f) + log1pf(expf(-fabsf(x)));
}
__device__ __forceinline__ float4 max4(float4 a, float4 b) {
    return make_float4(fmaxf(a.x,b.x), fmaxf(a.y,b.y), fmaxf(a.z,b.z), fmaxf(a.w,b.w));
}
__device__ __forceinline__ void h_split(float x, __half& hi, __half& lo) {
    hi = __float2half_rn(x);
    lo = __float2half_rn(x - __half2float(hi));
}
__device__ __forceinline__ void mma_f16(float* d, const unsigned* a, const unsigned* b) {
    asm volatile(
        "mma.sync.aligned.m16n8k16.row.col.f32.f16.f16.f32 "
        "{%0,%1,%2,%3}, {%4,%5,%6,%7}, {%8,%9}, {%0,%1,%2,%3};\n"
        : "+f"(d[0]), "+f"(d[1]), "+f"(d[2]), "+f"(d[3])
        : "r"(a[0]), "r"(a[1]), "r"(a[2]), "r"(a[3]), "r"(b[0]), "r"(b[1]));
}

// write 4 consecutive split values (hi/lo planes) at half-index idx (8B aligned)
__device__ __forceinline__ void store_split4(__half* ph, __half* pl, size_t idx, float4 v) {
    __half hb[4], lb[4];
    h_split(v.x, hb[0], lb[0]); h_split(v.y, hb[1], lb[1]);
    h_split(v.z, hb[2], lb[2]); h_split(v.w, hb[3], lb[3]);
    *(uint2*)&ph[idx] = *(uint2*)hb;
    *(uint2*)&pl[idx] = *(uint2*)lb;
}

// ---------------- setup ----------------
__global__ void embed_sp_kernel(const float* __restrict__ emb, const int* __restrict__ ids,
                                float* __restrict__ out, __half* __restrict__ oh,
                                __half* __restrict__ ol, int rows) {
    int t = blockIdx.x * blockDim.x + threadIdx.x;
    if (t >= rows * 32) return;
    int n = t >> 5, l = t & 31;
    float4 v = ((const float4*)emb)[ids[n] * 32 + l];
    float4 o = make_float4(sp(v.x), sp(v.y), sp(v.z), sp(v.w));
    ((float4*)out)[(size_t)n * 32 + l] = o;
    if (oh) store_split4(oh, ol, (size_t)n * 128 + l * 4, o);
}

__global__ void count_deg_kernel(const int* __restrict__ dst) {
    int e = blockIdx.x * blockDim.x + threadIdx.x;
    if (e < EE) atomicAdd(&g_deg[dst[e]], 1);
}

__global__ void scan1_kernel() {
    __shared__ int s[1024];
    int t = threadIdx.x;
    int n = blockIdx.x * 1024 + t;
    int v = (n < NN) ? g_deg[n] : 0;
    s[t] = v;
    __syncthreads();
    for (int off = 1; off < 1024; off <<= 1) {
        int add = (t >= off) ? s[t - off] : 0;
        __syncthreads();
        s[t] += add;
        __syncthreads();
    }
    if (n < NN) g_off[n] = s[t] - v;
    if (t == 1023) g_bsumA[blockIdx.x] = s[1023];
}

__global__ void scan2_kernel(int nblk) {
    if (threadIdx.x == 0) {
        int run = 0;
        for (int i = 0; i < nblk; i++) { int v = g_bsumA[i]; g_boff[i] = run; run += v; }
    }
}

__global__ void scan3_kernel() {
    int n = blockIdx.x * blockDim.x + threadIdx.x;
    if (n < NN) g_off[n] += g_boff[n >> 10];
    if (n == 0) g_off[NN] = EE;
}

__global__ void fill_csr_kernel(const int* __restrict__ src, const int* __restrict__ dst) {
    int e = blockIdx.x * blockDim.x + threadIdx.x;
    if (e >= EE) return;
    int d = dst[e];
    int pos = atomicAdd(&g_fill[d], 1);
    int idx = g_off[d] + pos;
    g_csr_src[idx] = src[e];
    g_csr_eid[idx] = e;
}

__global__ void bounds_kernel(const int* __restrict__ batch) {
    int n = blockIdx.x * blockDim.x + threadIdx.x;
    if (n >= NN) return;
    int b = batch[n];
    int prev = (n == 0) ? -1 : batch[n - 1];
    for (int g = prev + 1; g <= b; g++) g_gstart[g] = n;
    if (n == NN - 1)
        for (int g = b + 1; g <= GG; g++) g_gstart[g] = NN;
}

// W' transposed planes: comb_t[j][k] = comb[k][j], j in [0,256), k in [0,128)
__global__ void build_comb_kernel(const float* __restrict__ Wb) {
    int idx = blockIdx.x * blockDim.x + threadIdx.x;
    if (idx >= EMB * 2 * EMB) return;
    int k = idx >> 8, j = idx & 255;
    float v;
    if (j < EMB) v = Wb[k * EMB + j] - Wb[(k + EMB) * EMB + j];
    else         v = Wb[(k + EMB) * EMB + (j - EMB)];
    __half hi, lo; h_split(v, hi, lo);
    g_combh[j * 128 + k] = hi;
    g_combl[j * 128 + k] = lo;
}

// Wcat transposed planes: wcat_t[c][r] = wcat[r][c], c in [0,128), r in [0,256)
__global__ void build_wcat_kernel(const float* __restrict__ Wm, const float* __restrict__ We) {
    int idx = blockIdx.x * blockDim.x + threadIdx.x;
    if (idx >= 2 * EMB * EMB) return;
    int r = idx >> 7, c = idx & 127;
    float v = (r < EMB) ? Wm[r * EMB + c] : We[(r - EMB) * EMB + c];
    __half hi, lo; h_split(v, hi, lo);
    g_wcath[c * 256 + r] = hi;
    g_wcatl[c * 256 + r] = lo;
}

// ---------------- fp16 2-term-split tensor-core GEMM, double-buffered (R13) -------
// C[M x Nc] = A[M x K] @ B[K x Nc], with A planes [M][K], B planes TRANSPOSED [Nc][K].
// 128x128 block tile, 256 threads, warps 2(m) x 4(n), warp tile 64x32,
// mma m16n8k16, 3 mmas per tile (ah*bh + al*bh + ah*bl).
// smem k-permuted so each fragment pair is one conflict-free LDS.64.
// 2-stage smem pipeline; chunk loop unrolled x2 so buffer indices constant-fold.
__global__ __launch_bounds__(256, 2)
void gemm_tc(const __half* __restrict__ Ah, const __half* __restrict__ Al,
             const __half* __restrict__ Bh, const __half* __restrict__ Bl,
             float* __restrict__ C, int M, int K, int Nc,
             const float* __restrict__ bmsg, const float* __restrict__ bedge,
             const int* __restrict__ degp, float* __restrict__ out2) {
    __shared__ __half sAh[2][128][16], sAl[2][128][16];
    __shared__ __half sBh[2][128][16], sBl[2][128][16];

    const int tid  = threadIdx.x;
    const int lane = tid & 31;
    const int warp = tid >> 5;
    const int g    = lane >> 2;
    const int c    = lane & 3;
    const int wm   = warp >> 2;      // 0..1
    const int wn   = warp & 3;       // 0..3
    const int bm   = blockIdx.x * 128;
    const int bn   = blockIdx.y * 128;

    float acc[4][4][4];
#pragma unroll
    for (int mf = 0; mf < 4; mf++)
#pragma unroll
        for (int nf = 0; nf < 4; nf++)
#pragma unroll
            for (int i = 0; i < 4; i++) acc[mf][nf][i] = 0.f;

    // staging: thread -> (row ar, k-half hq); smem pos base spos
    const int ar = tid >> 1;
    const int hq = (tid & 1) * 4;      // gmem k offset base
    const int spos = (tid & 1) * 8;    // smem half-pos base
    const int arow = (bm + ar < M) ? (bm + ar) : 0;   // clamp (guarded at epilogue)
    const size_t aoff = (size_t)arow * K;
    const size_t boff = (size_t)(bn + ar) * K;

    const int chunks = K >> 4;   // 8 or 16, always even

    // prologue: stage chunk 0 into buffer 0
    {
        uint2 a0 = *(const uint2*)&Ah[aoff + hq], a1 = *(const uint2*)&Ah[aoff + hq + 8];
        uint2 b0 = *(const uint2*)&Al[aoff + hq], b1 = *(const uint2*)&Al[aoff + hq + 8];
        uint2 c0 = *(const uint2*)&Bh[boff + hq], c1 = *(const uint2*)&Bh[boff + hq + 8];
        uint2 d0 = *(const uint2*)&Bl[boff + hq], d1 = *(const uint2*)&Bl[boff + hq + 8];
        *(uint4*)&sAh[0][ar][spos] = make_uint4(a0.x, a1.x, a0.y, a1.y);
        *(uint4*)&sAl[0][ar][spos] = make_uint4(b0.x, b1.x, b0.y, b1.y);
        *(uint4*)&sBh[0][ar][spos] = make_uint4(c0.x, c1.x, c0.y, c1.y);
        *(uint4*)&sBl[0][ar][spos] = make_uint4(d0.x, d1.x, d0.y, d1.y);
    }
    __syncthreads();

#pragma unroll 2
    for (int ch = 0; ch < chunks; ch++) {
        int cur = ch & 1, nxt = cur ^ 1;

        // stage next chunk into the other buffer (overlaps this chunk's mma
        // across warps; registers are freed immediately)
        if (ch < chunks - 1) {
            int kb = (ch + 1) * 16;
            uint2 a0 = *(const uint2*)&Ah[aoff + kb + hq], a1 = *(const uint2*)&Ah[aoff + kb + hq + 8];
            uint2 b0 = *(const uint2*)&Al[aoff + kb + hq], b1 = *(const uint2*)&Al[aoff + kb + hq + 8];
            uint2 c0 = *(const uint2*)&Bh[boff + kb + hq], c1 = *(const uint2*)&Bh[boff + kb + hq + 8];
            uint2 d0 = *(const uint2*)&Bl[boff + kb + hq], d1 = *(const uint2*)&Bl[boff + kb + hq + 8];
            *(uint4*)&sAh[nxt][ar][spos] = make_uint4(a0.x, a1.x, a0.y, a1.y);
            *(uint4*)&sAl[nxt][ar][spos] = make_uint4(b0.x, b1.x, b0.y, b1.y);
            *(uint4*)&sBh[nxt][ar][spos] = make_uint4(c0.x, c1.x, c0.y, c1.y);
            *(uint4*)&sBl[nxt][ar][spos] = make_uint4(d0.x, d1.x, d0.y, d1.y);
        }

        // fragments + mma on current buffer
        unsigned a_h[4][4], a_l[4][4];
#pragma unroll
        for (int mf = 0; mf < 4; mf++) {
            int r0 = wm * 64 + mf * 16 + g;
            uint2 h0 = *(const uint2*)&sAh[cur][r0][c * 4];
            uint2 h1 = *(const uint2*)&sAh[cur][r0 + 8][c * 4];
            uint2 l0 = *(const uint2*)&sAl[cur][r0][c * 4];
            uint2 l1 = *(const uint2*)&sAl[cur][r0 + 8][c * 4];
            a_h[mf][0] = h0.x; a_h[mf][1] = h1.x; a_h[mf][2] = h0.y; a_h[mf][3] = h1.y;
            a_l[mf][0] = l0.x; a_l[mf][1] = l1.x; a_l[mf][2] = l0.y; a_l[mf][3] = l1.y;
        }
#pragma unroll
        for (int nf = 0; nf < 4; nf++) {
            int n0 = wn * 32 + nf * 8 + g;
            uint2 bhv = *(const uint2*)&sBh[cur][n0][c * 4];
            uint2 blv = *(const uint2*)&sBl[cur][n0][c * 4];
            unsigned bH[2] = {bhv.x, bhv.y};
            unsigned bL[2] = {blv.x, blv.y};
#pragma unroll
            for (int mf = 0; mf < 4; mf++) {
                mma_f16(acc[mf][nf], a_h[mf], bH);
                mma_f16(acc[mf][nf], a_l[mf], bH);
                mma_f16(acc[mf][nf], a_h[mf], bL);
            }
        }
        __syncthreads();
    }

    // epilogue: acc -> (row = base+g [+8], col = base+2c [+1])
    if (!bmsg) {
#pragma unroll
        for (int mf = 0; mf < 4; mf++) {
            int r0 = bm + wm * 64 + mf * 16 + g;
#pragma unroll
            for (int nf = 0; nf < 4; nf++) {
                int col = bn + wn * 32 + nf * 8 + c * 2;
                if (r0 < M)
                    *(float2*)&C[(size_t)r0 * Nc + col] = make_float2(acc[mf][nf][0], acc[mf][nf][1]);
                if (r0 + 8 < M)
                    *(float2*)&C[(size_t)(r0 + 8) * Nc + col] = make_float2(acc[mf][nf][2], acc[mf][nf][3]);
            }
        }
    } else {
        float bsv[4][2];
#pragma unroll
        for (int nf = 0; nf < 4; nf++) {
            int col = bn + wn * 32 + nf * 8 + c * 2;
            bsv[nf][0] = bmsg[col] + bedge[col];
            bsv[nf][1] = bmsg[col + 1] + bedge[col + 1];
        }
#pragma unroll
        for (int mf = 0; mf < 4; mf++) {
            int r0 = bm + wm * 64 + mf * 16 + g;
#pragma unroll
            for (int rr = 0; rr < 2; rr++) {
                int row = r0 + rr * 8;
                if (row < M) {
                    float dg = (float)degp[row];
#pragma unroll
                    for (int nf = 0; nf < 4; nf++) {
                        int col = bn + wn * 32 + nf * 8 + c * 2;
                        float x0 = acc[mf][nf][rr * 2 + 0];
                        float x1 = acc[mf][nf][rr * 2 + 1];
                        float2 old = *(const float2*)&C[(size_t)row * Nc + col];
                        float v0 = sp(x0 + dg * bsv[nf][0] + old.x);
                        float v1 = sp(x1 + dg * bsv[nf][1] + old.y);
                        *(float2*)&C[(size_t)row * Nc + col] = make_float2(v0, v1);
                        if (out2)
                            *(float2*)&out2[(size_t)row * Nc + col] = make_float2(v0, v1);
                    }
                }
            }
        }
    }
}

// ---------------- CSR aggregations (warp per node, no atomics) ----------------
// Fused: EdgeConv max over Q[src] AND sum of h_a[src] (same index list, doubled MLP).
// Writes h_b (+splits, +out2) and the U half of X (splits).
__global__ void agg_max_u_kernel(const float* __restrict__ b_bond, float* __restrict__ out2) {
    int nid = blockIdx.x * 8 + (threadIdx.x >> 5);
    if (nid >= NN) return;
    int l = threadIdx.x & 31;
    int o0 = g_off[nid], o1 = g_off[nid + 1];
    const float4* PQ4 = (const float4*)g_PQ;
    const float4* ha4 = (const float4*)g_ha;
    float4 res;
    float4 u = make_float4(0.f, 0.f, 0.f, 0.f);
    if (o1 > o0) {
        float4 m = make_float4(-FLT_MAX, -FLT_MAX, -FLT_MAX, -FLT_MAX);
        for (int i = o0; i < o1; i++) {
            int s = g_csr_src[i];
            float4 q = PQ4[(size_t)s * 64 + 32 + l];
            float4 a = ha4[(size_t)s * 32 + l];
            m = max4(m, q);
            u.x += a.x; u.y += a.y; u.z += a.z; u.w += a.w;
        }
        float4 p  = PQ4[(size_t)nid * 64 + l];
        float4 bb = ((const float4*)b_bond)[l];
        res = make_float4(sp(m.x + p.x + bb.x), sp(m.y + p.y + bb.y),
                          sp(m.z + p.z + bb.z), sp(m.w + p.w + bb.w));
    } else {
        res = make_float4(LN2F, LN2F, LN2F, LN2F);
    }
    ((float4*)g_hb)[(size_t)nid * 32 + l] = res;
    store_split4(g_hbh, g_hbl, (size_t)nid * 128 + l * 4, res);
    if (out2) ((float4*)out2)[(size_t)nid * 32 + l] = res;
    store_split4(g_Xh, g_Xl, (size_t)nid * 256 + l * 4, u);
}

// T half: sum of updated h_b[eid] for eid < NN, plus ln2 per constant edge.
__global__ void agg_t_kernel() {
    int nid = blockIdx.x * 8 + (threadIdx.x >> 5);
    if (nid >= NN) return;
    int l = threadIdx.x & 31;
    int o0 = g_off[nid], o1 = g_off[nid + 1];
    const float4* hb4 = (const float4*)g_hb;
    float4 t = make_float4(0.f, 0.f, 0.f, 0.f);
    float cge = 0.f;
    for (int i = o0; i < o1; i++) {
        int e = g_csr_eid[i];
        if (e < NN) {
            float4 bv = hb4[(size_t)e * 32 + l];
            t.x += bv.x; t.y += bv.y; t.z += bv.z; t.w += bv.w;
        } else cge += 1.f;
    }
    float cc = cge * LN2F;
    t.x += cc; t.y += cc; t.z += cc; t.w += cc;
    store_split4(g_Xh, g_Xl, (size_t)nid * 256 + 128 + l * 4, t);
}

// ---------------- fused pool + readout ----------
__global__ void pool_readout_kernel(const float* __restrict__ Wr1, const float* __restrict__ br1,
                                    const float* __restrict__ Wr2, const float* __restrict__ br2,
                                    const float* __restrict__ Wr3, const float* __restrict__ br3,
                                    float* __restrict__ out) {
    __shared__ float pv[128];
    __shared__ float h1[64];
    __shared__ float h2[64];
    __shared__ float red[2];
    int g = blockIdx.x;
    int t = threadIdx.x;
    int s = g_gstart[g], e = g_gstart[g + 1];
    float sum = 0.f;
    for (int n = s; n < e; n++) sum += g_ha[(size_t)n * 128 + t];
    pv[t] = sum;
    __syncthreads();
    if (t < 64) {
        float a1 = br1[t];
#pragma unroll 8
        for (int k = 0; k < 128; k++) a1 += pv[k] * Wr1[k * 64 + t];
        h1[t] = sp(a1);
    }
    __syncthreads();
    if (t < 64) {
        float a2 = br2[t];
#pragma unroll 8
        for (int k = 0; k < 64; k++) a2 += h1[k] * Wr2[k * 64 + t];
        h2[t] = sp(a2);
    }
    __syncthreads();
    if (t < 64) {
        float v = h2[t] * Wr3[t];
#pragma unroll
        for (int o = 16; o > 0; o >>= 1) v += __shfl_down_sync(0xffffffffu, v, o);
        if ((t & 31) == 0) red[t >> 5] = v;
    }
    __syncthreads();
    if (t == 0) out[g] = red[0] + red[1] + br3[0];
}

__global__ void tail_hb_kernel(float* __restrict__ out_hb) {
    int t = blockIdx.x * blockDim.x + threadIdx.x;
    if (t >= (EE - NN) * 32) return;
    ((float4*)out_hb)[(size_t)NN * 32 + t] = make_float4(LN2F, LN2F, LN2F, LN2F);
}

// ---------------- launch ----------------
extern "C" void kernel_launch(void* const* d_in, const int* in_sizes, int n_in,
                              void* d_out, int out_size) {
    const int*   x_ids      = (const int*)d_in[0];
    const int*   edge_attr  = (const int*)d_in[1];
    const int*   edge_index = (const int*)d_in[2];
    const int*   batch      = (const int*)d_in[3];
    const float* emb_atom   = (const float*)d_in[4];
    const float* emb_bond   = (const float*)d_in[5];
    const float* W_bond     = (const float*)d_in[6];
    const float* b_bond     = (const float*)d_in[7];
    const float* W_msg      = (const float*)d_in[8];
    const float* b_msg      = (const float*)d_in[9];
    const float* W_edge     = (const float*)d_in[10];
    const float* b_edge     = (const float*)d_in[11];
    const float* W_r1       = (const float*)d_in[12];
    const float* b_r1       = (const float*)d_in[13];
    const float* W_r2       = (const float*)d_in[14];
    const float* b_r2       = (const float*)d_in[15];
    const float* W_r3       = (const float*)d_in[16];
    const float* b_r3       = (const float*)d_in[17];

    const int* src = edge_index;
    const int* dst = edge_index + EE;

    float* out_g  = (float*)d_out;
    float* out_ha = out_g + GG;
    float* out_hb = out_ha + (size_t)NN * EMB;

    void *p_deg, *p_fill, *p_ha, *p_hb, *p_PQ;
    void *p_hbh, *p_hbl, *p_Xh, *p_Xl, *p_combh, *p_combl, *p_wcath, *p_wcatl;
    cudaGetSymbolAddress(&p_deg,   g_deg);
    cudaGetSymbolAddress(&p_fill,  g_fill);
    cudaGetSymbolAddress(&p_ha,    g_ha);
    cudaGetSymbolAddress(&p_hb,    g_hb);
    cudaGetSymbolAddress(&p_PQ,    g_PQ);
    cudaGetSymbolAddress(&p_hbh,   g_hbh);
    cudaGetSymbolAddress(&p_hbl,   g_hbl);
    cudaGetSymbolAddress(&p_Xh,    g_Xh);
    cudaGetSymbolAddress(&p_Xl,    g_Xl);
    cudaGetSymbolAddress(&p_combh, g_combh);
    cudaGetSymbolAddress(&p_combl, g_combl);
    cudaGetSymbolAddress(&p_wcath, g_wcath);
    cudaGetSymbolAddress(&p_wcatl, g_wcatl);

    const int T = 256;
    int blk_n32 = (NN * 32 + T - 1) / T;
    int blk_n   = (NN + T - 1) / T;
    int blk_e   = (EE + T - 1) / T;
    int blk_w   = (NN + 7) / 8;
    int gm128   = (NN + 127) / 128;      // 782
    int nblk_scan = (NN + 1023) / 1024;

    // --- setup A (launches 1-5), first GEMM at slot 6 for ncu -s 5 -c 1 ---
    cudaMemsetAsync(p_deg,  0, NN * sizeof(int));                               // 1
    cudaMemsetAsync(p_fill, 0, NN * sizeof(int));                               // 2
    embed_sp_kernel<<<blk_n32, T>>>(emb_atom, x_ids, (float*)p_ha,
                                    nullptr, nullptr, NN);                      // 3
    embed_sp_kernel<<<blk_n32, T>>>(emb_bond, edge_attr, (float*)p_hb,
                                    (__half*)p_hbh, (__half*)p_hbl, NN);        // 4
    build_comb_kernel<<<(EMB * 2 * EMB + T - 1) / T, T>>>(W_bond);              // 5

    dim3 gr1(gm128, 2);
    gemm_tc<<<gr1, T>>>((const __half*)p_hbh, (const __half*)p_hbl,
                        (const __half*)p_combh, (const __half*)p_combl,
                        (float*)p_PQ, NN, 128, 256,
                        nullptr, nullptr, nullptr, nullptr);                    // 6 <- profiled

    // constant tail of out_hb: independent of everything -> overlap with pipeline
    tail_hb_kernel<<<((EE - NN) * 32 + T - 1) / T, T>>>(out_hb);                // 7

    // --- setup B (independent of GEMM) ---
    count_deg_kernel<<<blk_e, T>>>(dst);
    scan1_kernel<<<nblk_scan, 1024>>>();
    scan2_kernel<<<1, 32>>>(nblk_scan);
    scan3_kernel<<<blk_n, T>>>();
    fill_csr_kernel<<<blk_e, T>>>(src, dst);
    bounds_kernel<<<blk_n, T>>>(batch);
    build_wcat_kernel<<<(2 * EMB * EMB + T - 1) / T, T>>>(W_msg, W_edge);

    for (int pass = 0; pass < 2; pass++) {
        bool last = (pass == 1);
        if (pass > 0) {
            gemm_tc<<<gr1, T>>>((const __half*)p_hbh, (const __half*)p_hbl,
                                (const __half*)p_combh, (const __half*)p_combl,
                                (float*)p_PQ, NN, 128, 256,
                                nullptr, nullptr, nullptr, nullptr);
        }
        agg_max_u_kernel<<<blk_w, T>>>(b_bond, last ? out_hb : nullptr);
        agg_t_kernel<<<blk_w, T>>>();
        dim3 gr2(gm128, 1);
        gemm_tc<<<gr2, T>>>((const __half*)p_Xh, (const __half*)p_Xl,
                            (const __half*)p_wcath, (const __half*)p_wcatl,
                            (float*)p_ha, NN, 256, 128,
                            b_msg, b_edge, (const int*)p_deg,
                            last ? out_ha : nullptr);
    }

    pool_readout_kernel<<<GG, 128>>>(W_r1, b_r1, W_r2, b_r2, W_r3, b_r3, out_g);
}

// round 17
// speedup vs baseline: 1.1565x; 1.1565x over previous
#include <cuda_runtime.h>
#include <cuda_fp16.h>
#include <math.h>
#include <float.h>

#define NN 100000
#define EE 400000
#define GG 4096
#define EMB 128
#define LN2F 0.6931471805599453f

// ---------------- scratch ----------------
__device__ float  g_ha  [NN * EMB];
__device__ float  g_hb  [NN * EMB];
__device__ float  g_PQ  [NN * 2 * EMB];     // [P | Q], pitch 256
__device__ __half g_hbh [NN * EMB];         // fp16 plane of h_b (A operand)
__device__ __half g_Xh  [NN * 2 * EMB];     // fp16 plane of X=[U|T]
__device__ __half g_combh[2 * EMB * EMB];   // W' hi = [W1-W2|W2]^T : [256][128]
__device__ __half g_combl[2 * EMB * EMB];   // W' lo
__device__ __half g_wcath[2 * EMB * EMB];   // Wcat^T hi : [128][256]
__device__ __half g_wcatl[2 * EMB * EMB];   // Wcat^T lo
__device__ int    g_deg [NN];
__device__ int    g_off [NN + 1];
__device__ int    g_fill[NN];
__device__ int    g_bsumA[128];
__device__ int    g_boff [128];
__device__ int    g_csr_src[EE];
__device__ int    g_csr_eid[EE];
__device__ int    g_gstart[GG + 1];

__device__ __forceinline__ float sp(float x) {
    return fmaxf(x, 0.f) + log1pf(expf(-fabsf(x)));
}
__device__ __forceinline__ float4 max4(float4 a, float4 b) {
    return make_float4(fmaxf(a.x,b.x), fmaxf(a.y,b.y), fmaxf(a.z,b.z), fmaxf(a.w,b.w));
}
__device__ __forceinline__ void h_split(float x, __half& hi, __half& lo) {
    hi = __float2half_rn(x);
    lo = __float2half_rn(x - __half2float(hi));
}
__device__ __forceinline__ void mma_f16(float* d, const unsigned* a, const unsigned* b) {
    asm volatile(
        "mma.sync.aligned.m16n8k16.row.col.f32.f16.f16.f32 "
        "{%0,%1,%2,%3}, {%4,%5,%6,%7}, {%8,%9}, {%0,%1,%2,%3};\n"
        : "+f"(d[0]), "+f"(d[1]), "+f"(d[2]), "+f"(d[3])
        : "r"(a[0]), "r"(a[1]), "r"(a[2]), "r"(a[3]), "r"(b[0]), "r"(b[1]));
}

// store 4 consecutive fp16 values (single plane) at half-index idx (8B aligned)
__device__ __forceinline__ void store_h4(__half* ph, size_t idx, float4 v) {
    __half hb[4];
    hb[0] = __float2half_rn(v.x); hb[1] = __float2half_rn(v.y);
    hb[2] = __float2half_rn(v.z); hb[3] = __float2half_rn(v.w);
    *(uint2*)&ph[idx] = *(uint2*)hb;
}

// ---------------- setup ----------------
__global__ void embed_sp_kernel(const float* __restrict__ emb, const int* __restrict__ ids,
                                float* __restrict__ out, __half* __restrict__ oh, int rows) {
    int t = blockIdx.x * blockDim.x + threadIdx.x;
    if (t >= rows * 32) return;
    int n = t >> 5, l = t & 31;
    float4 v = ((const float4*)emb)[ids[n] * 32 + l];
    float4 o = make_float4(sp(v.x), sp(v.y), sp(v.z), sp(v.w));
    ((float4*)out)[(size_t)n * 32 + l] = o;
    if (oh) store_h4(oh, (size_t)n * 128 + l * 4, o);
}

__global__ void count_deg_kernel(const int* __restrict__ dst) {
    int e = blockIdx.x * blockDim.x + threadIdx.x;
    if (e < EE) atomicAdd(&g_deg[dst[e]], 1);
}

__global__ void scan1_kernel() {
    __shared__ int s[1024];
    int t = threadIdx.x;
    int n = blockIdx.x * 1024 + t;
    int v = (n < NN) ? g_deg[n] : 0;
    s[t] = v;
    __syncthreads();
    for (int off = 1; off < 1024; off <<= 1) {
        int add = (t >= off) ? s[t - off] : 0;
        __syncthreads();
        s[t] += add;
        __syncthreads();
    }
    if (n < NN) g_off[n] = s[t] - v;
    if (t == 1023) g_bsumA[blockIdx.x] = s[1023];
}

__global__ void scan2_kernel(int nblk) {
    if (threadIdx.x == 0) {
        int run = 0;
        for (int i = 0; i < nblk; i++) { int v = g_bsumA[i]; g_boff[i] = run; run += v; }
    }
}

__global__ void scan3_kernel() {
    int n = blockIdx.x * blockDim.x + threadIdx.x;
    if (n < NN) g_off[n] += g_boff[n >> 10];
    if (n == 0) g_off[NN] = EE;
}

__global__ void fill_csr_kernel(const int* __restrict__ src, const int* __restrict__ dst) {
    int e = blockIdx.x * blockDim.x + threadIdx.x;
    if (e >= EE) return;
    int d = dst[e];
    int pos = atomicAdd(&g_fill[d], 1);
    int idx = g_off[d] + pos;
    g_csr_src[idx] = src[e];
    g_csr_eid[idx] = e;
}

__global__ void bounds_kernel(const int* __restrict__ batch) {
    int n = blockIdx.x * blockDim.x + threadIdx.x;
    if (n >= NN) return;
    int b = batch[n];
    int prev = (n == 0) ? -1 : batch[n - 1];
    for (int g = prev + 1; g <= b; g++) g_gstart[g] = n;
    if (n == NN - 1)
        for (int g = b + 1; g <= GG; g++) g_gstart[g] = NN;
}

// W' transposed planes: comb_t[j][k] = comb[k][j], j in [0,256), k in [0,128)
__global__ void build_comb_kernel(const float* __restrict__ Wb) {
    int idx = blockIdx.x * blockDim.x + threadIdx.x;
    if (idx >= EMB * 2 * EMB) return;
    int k = idx >> 8, j = idx & 255;
    float v;
    if (j < EMB) v = Wb[k * EMB + j] - Wb[(k + EMB) * EMB + j];
    else         v = Wb[(k + EMB) * EMB + (j - EMB)];
    __half hi, lo; h_split(v, hi, lo);
    g_combh[j * 128 + k] = hi;
    g_combl[j * 128 + k] = lo;
}

// Wcat transposed planes: wcat_t[c][r] = wcat[r][c], c in [0,128), r in [0,256)
__global__ void build_wcat_kernel(const float* __restrict__ Wm, const float* __restrict__ We) {
    int idx = blockIdx.x * blockDim.x + threadIdx.x;
    if (idx >= 2 * EMB * EMB) return;
    int r = idx >> 7, c = idx & 127;
    float v = (r < EMB) ? Wm[r * EMB + c] : We[(r - EMB) * EMB + c];
    __half hi, lo; h_split(v, hi, lo);
    g_wcath[c * 256 + r] = hi;
    g_wcatl[c * 256 + r] = lo;
}

// ---------- fp16 GEMM: A single-plane, B weight 2-plane (exact to A-rounding) ------
// C[M x Nc] = A[M x K] @ (Bh+Bl)[K x Nc], A plane [M][K], B planes TRANSPOSED [Nc][K].
// 128x128 block tile, 256 threads, warps 2(m) x 4(n), warp tile 64x32,
// mma m16n8k16, 2 mmas per tile (a*bh + a*bl).
// smem k-permuted -> each fragment pair is one conflict-free LDS.64.
// 2-stage smem pipeline; chunk loop unrolled x2 so buffer indices constant-fold.
__global__ __launch_bounds__(256, 2)
void gemm_tc(const __half* __restrict__ Ah,
             const __half* __restrict__ Bh, const __half* __restrict__ Bl,
             float* __restrict__ C, int M, int K, int Nc,
             const float* __restrict__ bmsg, const float* __restrict__ bedge,
             const int* __restrict__ degp, float* __restrict__ out2) {
    __shared__ __half sAh[2][128][16];
    __shared__ __half sBh[2][128][16], sBl[2][128][16];

    const int tid  = threadIdx.x;
    const int lane = tid & 31;
    const int warp = tid >> 5;
    const int g    = lane >> 2;
    const int c    = lane & 3;
    const int wm   = warp >> 2;      // 0..1
    const int wn   = warp & 3;       // 0..3
    const int bm   = blockIdx.x * 128;
    const int bn   = blockIdx.y * 128;

    float acc[4][4][4];
#pragma unroll
    for (int mf = 0; mf < 4; mf++)
#pragma unroll
        for (int nf = 0; nf < 4; nf++)
#pragma unroll
            for (int i = 0; i < 4; i++) acc[mf][nf][i] = 0.f;

    // staging: thread -> (row ar, k-half hq); smem pos base spos
    const int ar = tid >> 1;
    const int hq = (tid & 1) * 4;      // gmem k offset base (in units of 2 halves)
    const int spos = (tid & 1) * 8;    // smem half-pos base
    const int arow = (bm + ar < M) ? (bm + ar) : 0;   // clamp (guarded at epilogue)
    const size_t aoff = (size_t)arow * K;
    const size_t boff = (size_t)(bn + ar) * K;

    const int chunks = K >> 4;   // 8 or 16, always even

    // prologue: stage chunk 0 into buffer 0
    {
        uint2 a0 = *(const uint2*)&Ah[aoff + hq], a1 = *(const uint2*)&Ah[aoff + hq + 8];
        uint2 c0 = *(const uint2*)&Bh[boff + hq], c1 = *(const uint2*)&Bh[boff + hq + 8];
        uint2 d0 = *(const uint2*)&Bl[boff + hq], d1 = *(const uint2*)&Bl[boff + hq + 8];
        *(uint4*)&sAh[0][ar][spos] = make_uint4(a0.x, a1.x, a0.y, a1.y);
        *(uint4*)&sBh[0][ar][spos] = make_uint4(c0.x, c1.x, c0.y, c1.y);
        *(uint4*)&sBl[0][ar][spos] = make_uint4(d0.x, d1.x, d0.y, d1.y);
    }
    __syncthreads();

#pragma unroll 2
    for (int ch = 0; ch < chunks; ch++) {
        int cur = ch & 1, nxt = cur ^ 1;

        // stage next chunk into the other buffer
        if (ch < chunks - 1) {
            int kb = (ch + 1) * 16;
            uint2 a0 = *(const uint2*)&Ah[aoff + kb + hq], a1 = *(const uint2*)&Ah[aoff + kb + hq + 8];
            uint2 c0 = *(const uint2*)&Bh[boff + kb + hq], c1 = *(const uint2*)&Bh[boff + kb + hq + 8];
            uint2 d0 = *(const uint2*)&Bl[boff + kb + hq], d1 = *(const uint2*)&Bl[boff + kb + hq + 8];
            *(uint4*)&sAh[nxt][ar][spos] = make_uint4(a0.x, a1.x, a0.y, a1.y);
            *(uint4*)&sBh[nxt][ar][spos] = make_uint4(c0.x, c1.x, c0.y, c1.y);
            *(uint4*)&sBl[nxt][ar][spos] = make_uint4(d0.x, d1.x, d0.y, d1.y);
        }

        // fragments + mma on current buffer
        unsigned a_f[4][4];
#pragma unroll
        for (int mf = 0; mf < 4; mf++) {
            int r0 = wm * 64 + mf * 16 + g;
            uint2 h0 = *(const uint2*)&sAh[cur][r0][c * 4];
            uint2 h1 = *(const uint2*)&sAh[cur][r0 + 8][c * 4];
            a_f[mf][0] = h0.x; a_f[mf][1] = h1.x; a_f[mf][2] = h0.y; a_f[mf][3] = h1.y;
        }
#pragma unroll
        for (int nf = 0; nf < 4; nf++) {
            int n0 = wn * 32 + nf * 8 + g;
            uint2 bhv = *(const uint2*)&sBh[cur][n0][c * 4];
            uint2 blv = *(const uint2*)&sBl[cur][n0][c * 4];
            unsigned bH[2] = {bhv.x, bhv.y};
            unsigned bL[2] = {blv.x, blv.y};
#pragma unroll
            for (int mf = 0; mf < 4; mf++) {
                mma_f16(acc[mf][nf], a_f[mf], bH);
                mma_f16(acc[mf][nf], a_f[mf], bL);
            }
        }
        __syncthreads();
    }

    // epilogue: acc -> (row = base+g [+8], col = base+2c [+1])
    if (!bmsg) {
#pragma unroll
        for (int mf = 0; mf < 4; mf++) {
            int r0 = bm + wm * 64 + mf * 16 + g;
#pragma unroll
            for (int nf = 0; nf < 4; nf++) {
                int col = bn + wn * 32 + nf * 8 + c * 2;
                if (r0 < M)
                    *(float2*)&C[(size_t)r0 * Nc + col] = make_float2(acc[mf][nf][0], acc[mf][nf][1]);
                if (r0 + 8 < M)
                    *(float2*)&C[(size_t)(r0 + 8) * Nc + col] = make_float2(acc[mf][nf][2], acc[mf][nf][3]);
            }
        }
    } else {
        float bsv[4][2];
#pragma unroll
        for (int nf = 0; nf < 4; nf++) {
            int col = bn + wn * 32 + nf * 8 + c * 2;
            bsv[nf][0] = bmsg[col] + bedge[col];
            bsv[nf][1] = bmsg[col + 1] + bedge[col + 1];
        }
#pragma unroll
        for (int mf = 0; mf < 4; mf++) {
            int r0 = bm + wm * 64 + mf * 16 + g;
#pragma unroll
            for (int rr = 0; rr < 2; rr++) {
                int row = r0 + rr * 8;
                if (row < M) {
                    float dg = (float)degp[row];
#pragma unroll
                    for (int nf = 0; nf < 4; nf++) {
                        int col = bn + wn * 32 + nf * 8 + c * 2;
                        float x0 = acc[mf][nf][rr * 2 + 0];
                        float x1 = acc[mf][nf][rr * 2 + 1];
                        float2 old = *(const float2*)&C[(size_t)row * Nc + col];
                        float v0 = sp(x0 + dg * bsv[nf][0] + old.x);
                        float v1 = sp(x1 + dg * bsv[nf][1] + old.y);
                        *(float2*)&C[(size_t)row * Nc + col] = make_float2(v0, v1);
                        if (out2)
                            *(float2*)&out2[(size_t)row * Nc + col] = make_float2(v0, v1);
                    }
                }
            }
        }
    }
}

// ---------------- CSR aggregations (warp per node, no atomics) ----------------
// Fused: EdgeConv max over Q[src] AND sum of h_a[src] (same index list, doubled MLP).
__global__ void agg_max_u_kernel(const float* __restrict__ b_bond, float* __restrict__ out2) {
    int nid = blockIdx.x * 8 + (threadIdx.x >> 5);
    if (nid >= NN) return;
    int l = threadIdx.x & 31;
    int o0 = g_off[nid], o1 = g_off[nid + 1];
    const float4* PQ4 = (const float4*)g_PQ;
    const float4* ha4 = (const float4*)g_ha;
    float4 res;
    float4 u = make_float4(0.f, 0.f, 0.f, 0.f);
    if (o1 > o0) {
        float4 m = make_float4(-FLT_MAX, -FLT_MAX, -FLT_MAX, -FLT_MAX);
        for (int i = o0; i < o1; i++) {
            int s = g_csr_src[i];
            float4 q = PQ4[(size_t)s * 64 + 32 + l];
            float4 a = ha4[(size_t)s * 32 + l];
            m = max4(m, q);
            u.x += a.x; u.y += a.y; u.z += a.z; u.w += a.w;
        }
        float4 p  = PQ4[(size_t)nid * 64 + l];
        float4 bb = ((const float4*)b_bond)[l];
        res = make_float4(sp(m.x + p.x + bb.x), sp(m.y + p.y + bb.y),
                          sp(m.z + p.z + bb.z), sp(m.w + p.w + bb.w));
    } else {
        res = make_float4(LN2F, LN2F, LN2F, LN2F);
    }
    ((float4*)g_hb)[(size_t)nid * 32 + l] = res;
    store_h4(g_hbh, (size_t)nid * 128 + l * 4, res);
    if (out2) ((float4*)out2)[(size_t)nid * 32 + l] = res;
    store_h4(g_Xh, (size_t)nid * 256 + l * 4, u);
}

// T half: sum of updated h_b[eid] for eid < NN, plus ln2 per constant edge.
__global__ void agg_t_kernel() {
    int nid = blockIdx.x * 8 + (threadIdx.x >> 5);
    if (nid >= NN) return;
    int l = threadIdx.x & 31;
    int o0 = g_off[nid], o1 = g_off[nid + 1];
    const float4* hb4 = (const float4*)g_hb;
    float4 t = make_float4(0.f, 0.f, 0.f, 0.f);
    float cge = 0.f;
    for (int i = o0; i < o1; i++) {
        int e = g_csr_eid[i];
        if (e < NN) {
            float4 bv = hb4[(size_t)e * 32 + l];
            t.x += bv.x; t.y += bv.y; t.z += bv.z; t.w += bv.w;
        } else cge += 1.f;
    }
    float cc = cge * LN2F;
    t.x += cc; t.y += cc; t.z += cc; t.w += cc;
    store_h4(g_Xh, (size_t)nid * 256 + 128 + l * 4, t);
}

// ---------------- fused pool + readout ----------
__global__ void pool_readout_kernel(const float* __restrict__ Wr1, const float* __restrict__ br1,
                                    const float* __restrict__ Wr2, const float* __restrict__ br2,
                                    const float* __restrict__ Wr3, const float* __restrict__ br3,
                                    float* __restrict__ out) {
    __shared__ float pv[128];
    __shared__ float h1[64];
    __shared__ float h2[64];
    __shared__ float red[2];
    int g = blockIdx.x;
    int t = threadIdx.x;
    int s = g_gstart[g], e = g_gstart[g + 1];
    float sum = 0.f;
    for (int n = s; n < e; n++) sum += g_ha[(size_t)n * 128 + t];
    pv[t] = sum;
    __syncthreads();
    if (t < 64) {
        float a1 = br1[t];
#pragma unroll 8
        for (int k = 0; k < 128; k++) a1 += pv[k] * Wr1[k * 64 + t];
        h1[t] = sp(a1);
    }
    __syncthreads();
    if (t < 64) {
        float a2 = br2[t];
#pragma unroll 8
        for (int k = 0; k < 64; k++) a2 += h1[k] * Wr2[k * 64 + t];
        h2[t] = sp(a2);
    }
    __syncthreads();
    if (t < 64) {
        float v = h2[t] * Wr3[t];
#pragma unroll
        for (int o = 16; o > 0; o >>= 1) v += __shfl_down_sync(0xffffffffu, v, o);
        if ((t & 31) == 0) red[t >> 5] = v;
    }
    __syncthreads();
    if (t == 0) out[g] = red[0] + red[1] + br3[0];
}

__global__ void tail_hb_kernel(float* __restrict__ out_hb) {
    int t = blockIdx.x * blockDim.x + threadIdx.x;
    if (t >= (EE - NN) * 32) return;
    ((float4*)out_hb)[(size_t)NN * 32 + t] = make_float4(LN2F, LN2F, LN2F, LN2F);
}

// ---------------- launch ----------------
extern "C" void kernel_launch(void* const* d_in, const int* in_sizes, int n_in,
                              void* d_out, int out_size) {
    const int*   x_ids      = (const int*)d_in[0];
    const int*   edge_attr  = (const int*)d_in[1];
    const int*   edge_index = (const int*)d_in[2];
    const int*   batch      = (const int*)d_in[3];
    const float* emb_atom   = (const float*)d_in[4];
    const float* emb_bond   = (const float*)d_in[5];
    const float* W_bond     = (const float*)d_in[6];
    const float* b_bond     = (const float*)d_in[7];
    const float* W_msg      = (const float*)d_in[8];
    const float* b_msg      = (const float*)d_in[9];
    const float* W_edge     = (const float*)d_in[10];
    const float* b_edge     = (const float*)d_in[11];
    const float* W_r1       = (const float*)d_in[12];
    const float* b_r1       = (const float*)d_in[13];
    const float* W_r2       = (const float*)d_in[14];
    const float* b_r2       = (const float*)d_in[15];
    const float* W_r3       = (const float*)d_in[16];
    const float* b_r3       = (const float*)d_in[17];

    const int* src = edge_index;
    const int* dst = edge_index + EE;

    float* out_g  = (float*)d_out;
    float* out_ha = out_g + GG;
    float* out_hb = out_ha + (size_t)NN * EMB;

    void *p_deg, *p_fill, *p_ha, *p_hb, *p_PQ;
    void *p_hbh, *p_Xh, *p_combh, *p_combl, *p_wcath, *p_wcatl;
    cudaGetSymbolAddress(&p_deg,   g_deg);
    cudaGetSymbolAddress(&p_fill,  g_fill);
    cudaGetSymbolAddress(&p_ha,    g_ha);
    cudaGetSymbolAddress(&p_hb,    g_hb);
    cudaGetSymbolAddress(&p_PQ,    g_PQ);
    cudaGetSymbolAddress(&p_hbh,   g_hbh);
    cudaGetSymbolAddress(&p_Xh,    g_Xh);
    cudaGetSymbolAddress(&p_combh, g_combh);
    cudaGetSymbolAddress(&p_combl, g_combl);
    cudaGetSymbolAddress(&p_wcath, g_wcath);
    cudaGetSymbolAddress(&p_wcatl, g_wcatl);

    const int T = 256;
    int blk_n32 = (NN * 32 + T - 1) / T;
    int blk_n   = (NN + T - 1) / T;
    int blk_e   = (EE + T - 1) / T;
    int blk_w   = (NN + 7) / 8;
    int gm128   = (NN + 127) / 128;      // 782
    int nblk_scan = (NN + 1023) / 1024;

    // --- setup A (launches 1-5), first GEMM at slot 6 for ncu -s 5 -c 1 ---
    cudaMemsetAsync(p_deg,  0, NN * sizeof(int));                               // 1
    cudaMemsetAsync(p_fill, 0, NN * sizeof(int));                               // 2
    embed_sp_kernel<<<blk_n32, T>>>(emb_atom, x_ids, (float*)p_ha, nullptr, NN);// 3
    embed_sp_kernel<<<blk_n32, T>>>(emb_bond, edge_attr, (float*)p_hb,
                                    (__half*)p_hbh, NN);                        // 4
    build_comb_kernel<<<(EMB * 2 * EMB + T - 1) / T, T>>>(W_bond);              // 5

    dim3 gr1(gm128, 2);
    gemm_tc<<<gr1, T>>>((const __half*)p_hbh,
                        (const __half*)p_combh, (const __half*)p_combl,
                        (float*)p_PQ, NN, 128, 256,
                        nullptr, nullptr, nullptr, nullptr);                    // 6 <- profiled

    // constant tail of out_hb: independent of everything -> overlap with pipeline
    tail_hb_kernel<<<((EE - NN) * 32 + T - 1) / T, T>>>(out_hb);                // 7

    // --- setup B (independent of GEMM) ---
    count_deg_kernel<<<blk_e, T>>>(dst);
    scan1_kernel<<<nblk_scan, 1024>>>();
    scan2_kernel<<<1, 32>>>(nblk_scan);
    scan3_kernel<<<blk_n, T>>>();
    fill_csr_kernel<<<blk_e, T>>>(src, dst);
    bounds_kernel<<<blk_n, T>>>(batch);
    build_wcat_kernel<<<(2 * EMB * EMB + T - 1) / T, T>>>(W_msg, W_edge);

    for (int pass = 0; pass < 2; pass++) {
        bool last = (pass == 1);
        if (pass > 0) {
            gemm_tc<<<gr1, T>>>((const __half*)p_hbh,
                                (const __half*)p_combh, (const __half*)p_combl,
                                (float*)p_PQ, NN, 128, 256,
                                nullptr, nullptr, nullptr, nullptr);
        }
        agg_max_u_kernel<<<blk_w, T>>>(b_bond, last ? out_hb : nullptr);
        agg_t_kernel<<<blk_w, T>>>();
        dim3 gr2(gm128, 1);
        gemm_tc<<<gr2, T>>>((const __half*)p_Xh,
                            (const __half*)p_wcath, (const __half*)p_wcatl,
                            (float*)p_ha, NN, 256, 128,
                            b_msg, b_edge, (const int*)p_deg,
                            last ? out_ha : nullptr);
    }

    pool_readout_kernel<<<GG, 128>>>(W_r1, b_r1, W_r2, b_r2, W_r3, b_r3, out_g);
}